// round 1
// baseline (speedup 1.0000x reference)
#include <cuda_runtime.h>

#define HH 128
#define WW 128
#define HW (HH * WW)
#define BB 4

// Scratch (allocation-free rule: __device__ globals)
__device__ float g_buf1[(size_t)BB * 64 * HW];   // offset_1
__device__ float g_buf2[(size_t)BB * 64 * HW];   // offset_2
__device__ float g_om  [(size_t)BB * 27 * HW];   // offset/mask conv output
__device__ float g_align[(size_t)BB * 64 * HW];  // dcn output (pre out-conv)

// ---------------------------------------------------------------------------
// Generic 3x3 SAME conv, stride 1, NCHW, OIHW weights.
// Tile: 64(w) x 16(h) pixels, 256 threads, thread = 1x4 pixel microtile x OCB
// output channels. IC may be 128 (concat of two 64-channel tensors in0,in1).
// ACT: 0 = none, 1 = leaky relu 0.1, 2 = relu
// ---------------------------------------------------------------------------
template<int IC, int OCB, int ACT>
__global__ __launch_bounds__(256)
void conv3x3_kernel(const float* __restrict__ in0, const float* __restrict__ in1,
                    const float* __restrict__ w, const float* __restrict__ bias,
                    float* __restrict__ out, int n_ocb)
{
    __shared__ float patch[18 * 66];
    __shared__ float wsm[OCB * 9];

    const int tid = threadIdx.x;
    const int tx  = tid & 15;        // 16 threads across -> 64 px (4 each)
    const int ty  = tid >> 4;        // 16 rows
    const int bx  = blockIdx.x * 64;
    const int by  = blockIdx.y * 16;
    const int b   = blockIdx.z / n_ocb;
    const int ocb = blockIdx.z - b * n_ocb;

    float acc[OCB][4];
#pragma unroll
    for (int o = 0; o < OCB; ++o)
#pragma unroll
        for (int p = 0; p < 4; ++p) acc[o][p] = 0.f;

    for (int ic = 0; ic < IC; ++ic) {
        const float* src;
        if (IC > 64 && ic >= 64)
            src = in1 + ((size_t)b * 64 + (ic - 64)) * HW;
        else
            src = in0 + ((size_t)b * 64 + ic) * HW;

        // stage 18x66 halo patch for this input channel
        for (int i = tid; i < 18 * 66; i += 256) {
            int r = i / 66, c = i - r * 66;
            int gy = by + r - 1, gx = bx + c - 1;
            float v = 0.f;
            if ((unsigned)gy < HH && (unsigned)gx < WW) v = src[gy * WW + gx];
            patch[i] = v;
        }
        // stage weights for this ic, OCB output channels
        if (tid < OCB * 9) {
            int oc = ocb * OCB + tid / 9;
            int k  = tid - (tid / 9) * 9;
            wsm[tid] = w[((size_t)oc * IC + ic) * 9 + k];
        }
        __syncthreads();

        float v[3][6];
#pragma unroll
        for (int r = 0; r < 3; ++r)
#pragma unroll
            for (int c = 0; c < 6; ++c)
                v[r][c] = patch[(ty + r) * 66 + tx * 4 + c];

#pragma unroll
        for (int o = 0; o < OCB; ++o) {
#pragma unroll
            for (int ky = 0; ky < 3; ++ky)
#pragma unroll
                for (int kx = 0; kx < 3; ++kx) {
                    float wv = wsm[o * 9 + ky * 3 + kx];   // warp-uniform broadcast
#pragma unroll
                    for (int p = 0; p < 4; ++p)
                        acc[o][p] = fmaf(v[ky][kx + p], wv, acc[o][p]);
                }
        }
        __syncthreads();
    }

    const int OC = n_ocb * OCB;
    const int py = by + ty;
    const int px = bx + tx * 4;
#pragma unroll
    for (int o = 0; o < OCB; ++o) {
        int oc = ocb * OCB + o;
        float bv = bias[oc];
        float rr[4];
#pragma unroll
        for (int p = 0; p < 4; ++p) {
            float vv = acc[o][p] + bv;
            if (ACT == 1) vv = (vv >= 0.f) ? vv : 0.1f * vv;
            if (ACT == 2) vv = fmaxf(vv, 0.f);
            rr[p] = vv;
        }
        float4 r4; r4.x = rr[0]; r4.y = rr[1]; r4.z = rr[2]; r4.w = rr[3];
        *reinterpret_cast<float4*>(&out[((size_t)b * OC + oc) * HW + (size_t)py * WW + px]) = r4;
    }
}

// ---------------------------------------------------------------------------
// Deformable conv core. Thread = 1 pixel, 64 output-channel accumulators.
// Per tap k: stage 64x64 weight slice transposed [c][oc] into smem, compute
// bilinear corner indices + (mask-folded) weights once, then for each input
// channel: 4 coalesced corner loads -> sample s, broadcast-LDS.128 weights,
// 64 FMAs.
// ---------------------------------------------------------------------------
__global__ __launch_bounds__(256)
void dcn_kernel(const float* __restrict__ x, const float* __restrict__ om,
                const float* __restrict__ wd, const float* __restrict__ bias,
                float* __restrict__ out)
{
    __shared__ float wk[64 * 64];    // [c][oc] for current k

    const int tid  = threadIdx.x;
    const int px0  = tid & 127;      // 128 px across (full row)
    const int wrow = tid >> 7;       // 2 rows per block
    const int b    = blockIdx.y;
    const int py0  = blockIdx.x * 2 + wrow;
    const int hw   = py0 * WW + px0;

    const float* omb = om + (size_t)b * 27 * HW;
    const float* xb  = x  + (size_t)b * 64 * HW;

    float acc[64];
#pragma unroll
    for (int o = 0; o < 64; ++o) acc[o] = 0.f;

    for (int k = 0; k < 9; ++k) {
        __syncthreads();
        for (int i = tid; i < 4096; i += 256) {
            int c = i >> 6, oc = i & 63;
            wk[i] = wd[((size_t)oc * 64 + c) * 9 + k];   // transpose to [c][oc]
        }
        __syncthreads();

        float oy = omb[(size_t)k * HW + hw];
        float ox = omb[(size_t)(9 + k) * HW + hw];
        float mr = omb[(size_t)(18 + k) * HW + hw];
        float m  = 1.f / (1.f + __expf(-mr));

        int   ky = k / 3, kx = k - ky * 3;
        float py = (float)(py0 - 1 + ky) + oy;
        float px = (float)(px0 - 1 + kx) + ox;
        float y0f = floorf(py), x0f = floorf(px);
        float ly = py - y0f, lx = px - x0f;
        int y0 = (int)y0f, x0 = (int)x0f;
        int y1 = y0 + 1,   x1 = x0 + 1;

        float vy0 = (y0 >= 0 && y0 <= HH - 1) ? 1.f : 0.f;
        float vy1 = (y1 >= 0 && y1 <= HH - 1) ? 1.f : 0.f;
        float vx0 = (x0 >= 0 && x0 <= WW - 1) ? 1.f : 0.f;
        float vx1 = (x1 >= 0 && x1 <= WW - 1) ? 1.f : 0.f;
        int y0c = min(max(y0, 0), HH - 1), y1c = min(max(y1, 0), HH - 1);
        int x0c = min(max(x0, 0), WW - 1), x1c = min(max(x1, 0), WW - 1);

        float w00 = (1.f - ly) * (1.f - lx) * m * vy0 * vx0;
        float w01 = (1.f - ly) * lx         * m * vy0 * vx1;
        float w10 = ly         * (1.f - lx) * m * vy1 * vx0;
        float w11 = ly         * lx         * m * vy1 * vx1;

        int i00 = y0c * WW + x0c, i01 = y0c * WW + x1c;
        int i10 = y1c * WW + x0c, i11 = y1c * WW + x1c;

        for (int c = 0; c < 64; ++c) {
            const float* xc = xb + (size_t)c * HW;
            float s = w00 * xc[i00] + w01 * xc[i01] + w10 * xc[i10] + w11 * xc[i11];
            const float4* wr = reinterpret_cast<const float4*>(&wk[c * 64]);
#pragma unroll
            for (int o4 = 0; o4 < 16; ++o4) {
                float4 wv = wr[o4];                      // warp-uniform broadcast
                acc[o4 * 4 + 0] = fmaf(s, wv.x, acc[o4 * 4 + 0]);
                acc[o4 * 4 + 1] = fmaf(s, wv.y, acc[o4 * 4 + 1]);
                acc[o4 * 4 + 2] = fmaf(s, wv.z, acc[o4 * 4 + 2]);
                acc[o4 * 4 + 3] = fmaf(s, wv.w, acc[o4 * 4 + 3]);
            }
        }
    }

#pragma unroll
    for (int o = 0; o < 64; ++o)
        out[((size_t)b * 64 + o) * HW + hw] = acc[o] + bias[o];
}

// ---------------------------------------------------------------------------
extern "C" void kernel_launch(void* const* d_in, const int* in_sizes, int n_in,
                              void* d_out, int out_size)
{
    const float* x        = (const float*)d_in[0];
    const float* x_neigh  = (const float*)d_in[1];
    const float* offset_t = (const float*)d_in[2];
    const float* w_off1   = (const float*)d_in[3];
    const float* b_off1   = (const float*)d_in[4];
    const float* w_off2   = (const float*)d_in[5];
    const float* b_off2   = (const float*)d_in[6];
    const float* w_off3   = (const float*)d_in[7];
    const float* b_off3   = (const float*)d_in[8];
    const float* w_om     = (const float*)d_in[9];
    const float* b_om     = (const float*)d_in[10];
    const float* w_dcn    = (const float*)d_in[11];
    const float* b_dcn    = (const float*)d_in[12];
    const float* w_outw   = (const float*)d_in[13];
    const float* b_outw   = (const float*)d_in[14];

    float* out        = (float*)d_out;
    float* out_align  = out;                              // (4,64,128,128)
    float* out_offset = out + (size_t)BB * 64 * HW;       // (4,64,128,128)

    float *p1, *p2, *pom, *pal;
    cudaGetSymbolAddress((void**)&p1,  g_buf1);
    cudaGetSymbolAddress((void**)&p2,  g_buf2);
    cudaGetSymbolAddress((void**)&pom, g_om);
    cudaGetSymbolAddress((void**)&pal, g_align);

    dim3 blk(256);
    dim3 g64(2, 8, BB * 4);   // 64 out-ch, OCB=16 -> 4 oc-blocks
    dim3 gom(2, 8, BB * 3);   // 27 out-ch, OCB=9  -> 3 oc-blocks

    // offset_1 = lrelu(conv(concat(x, x_neigh)))
    conv3x3_kernel<128, 16, 1><<<g64, blk>>>(x, x_neigh, w_off1, b_off1, p1, 4);
    // offset_2 = lrelu(conv(concat(offset_1, offset_t)))
    conv3x3_kernel<128, 16, 1><<<g64, blk>>>(p1, offset_t, w_off2, b_off2, p2, 4);
    // offset = lrelu(conv(offset_2))  -> second half of d_out
    conv3x3_kernel<64, 16, 1><<<g64, blk>>>(p2, nullptr, w_off3, b_off3, out_offset, 4);
    // om = conv(offset), 27 channels, no activation
    conv3x3_kernel<64, 9, 0><<<gom, blk>>>(out_offset, nullptr, w_om, b_om, pom, 3);
    // deformable conv core
    dim3 gd(64, BB);
    dcn_kernel<<<gd, blk>>>(x, pom, w_dcn, b_dcn, pal);
    // align_feats = relu(conv(align)) -> first half of d_out
    conv3x3_kernel<64, 16, 2><<<g64, blk>>>(pal, nullptr, w_outw, b_outw, out_align, 4);
}

// round 2
// speedup vs baseline: 1.3266x; 1.3266x over previous
#include <cuda_runtime.h>

#define HH 128
#define WW 128
#define HW (HH * WW)
#define BB 4

typedef unsigned long long ull;

__device__ __forceinline__ ull pack2(float lo, float hi) {
    ull r; asm("mov.b64 %0,{%1,%2};" : "=l"(r) : "f"(lo), "f"(hi)); return r;
}
__device__ __forceinline__ float2 unpack2(ull v) {
    float2 r; asm("mov.b64 {%0,%1},%2;" : "=f"(r.x), "=f"(r.y) : "l"(v)); return r;
}
// d = a*b + d  (two independent fp32 FMAs per instruction)
__device__ __forceinline__ void fma2(ull& d, ull a, ull b) {
    asm("fma.rn.f32x2 %0,%1,%2,%0;" : "+l"(d) : "l"(a), "l"(b));
}

// Scratch (allocation-free rule: __device__ globals)
__device__ float g_buf1[(size_t)BB * 64 * HW];   // offset_1
__device__ float g_buf2[(size_t)BB * 64 * HW];   // offset_2
__device__ float g_om  [(size_t)BB * 27 * HW];   // offset/mask conv output
__device__ float g_align[(size_t)BB * 64 * HW];  // dcn output (pre out-conv)

// ---------------------------------------------------------------------------
// 3x3 SAME conv, NCHW, OIHW. Tile 64(w) x 16(h), 256 threads,
// thread = 1x4 px x OCB output channels (accumulated as f32x2 oc-pairs).
// 4 input channels staged per sync phase. IC may be 128 (two-pointer concat).
// ACT: 0 none, 1 lrelu(0.1), 2 relu.
// ---------------------------------------------------------------------------
template<int IC, int OCB, int ACT>
__global__ __launch_bounds__(256, 2)
void conv3x3_kernel(const float* __restrict__ in0, const float* __restrict__ in1,
                    const float* __restrict__ w, const float* __restrict__ bias,
                    float* __restrict__ out, int n_ocb, int OC)
{
    constexpr int ICS = 4;
    constexpr int NP  = OCB / 2;          // oc pairs
    constexpr int RS  = 68;               // padded patch row stride (mult of 4)

    __shared__ __align__(16) float patch[ICS][18 * RS];
    __shared__ __align__(16) float wsm[ICS][9][OCB];

    const int tid = threadIdx.x;
    const int tx  = tid & 15;
    const int ty  = tid >> 4;
    const int bx  = blockIdx.x * 64;
    const int by  = blockIdx.y * 16;
    const int b   = blockIdx.z / n_ocb;
    const int ocb = blockIdx.z - b * n_ocb;
    const int oc0 = ocb * OCB;

    ull acc[NP][4];
#pragma unroll
    for (int o = 0; o < NP; ++o)
#pragma unroll
        for (int p = 0; p < 4; ++p) acc[o][p] = 0ull;

    for (int ic0 = 0; ic0 < IC; ic0 += ICS) {
        __syncthreads();
        // stage 4 halo patches
        for (int i = tid; i < ICS * 18 * RS; i += 256) {
            int ics = i / (18 * RS);
            int r2  = i - ics * (18 * RS);
            int r   = r2 / RS, c = r2 - r * RS;
            int gy = by + r - 1, gx = bx + c - 1;
            float v = 0.f;
            if (c < 66 && (unsigned)gy < HH && (unsigned)gx < WW) {
                int ic = ic0 + ics;
                const float* src;
                if (IC > 64 && ic >= 64)
                    src = in1 + ((size_t)b * 64 + (ic - 64)) * HW;
                else
                    src = in0 + ((size_t)b * 64 + ic) * HW;
                v = src[gy * WW + gx];
            }
            patch[ics][r2] = v;
        }
        // stage weights (oc contiguous for packed loads)
        for (int i = tid; i < ICS * 9 * OCB; i += 256) {
            int ics = i / (9 * OCB);
            int r   = i - ics * (9 * OCB);
            int k   = r / OCB;
            int oc  = r - k * OCB;
            int ocg = oc0 + oc;
            wsm[ics][k][oc] = (ocg < OC) ? w[((size_t)ocg * IC + ic0 + ics) * 9 + k] : 0.f;
        }
        __syncthreads();

#pragma unroll
        for (int ics = 0; ics < ICS; ++ics) {
            float v[3][6];
            const float* prow = patch[ics];
#pragma unroll
            for (int r = 0; r < 3; ++r) {
                int base = (ty + r) * RS + tx * 4;
                float4 v4 = *reinterpret_cast<const float4*>(&prow[base]);
                float2 v2 = *reinterpret_cast<const float2*>(&prow[base + 4]);
                v[r][0] = v4.x; v[r][1] = v4.y; v[r][2] = v4.z; v[r][3] = v4.w;
                v[r][4] = v2.x; v[r][5] = v2.y;
            }
#pragma unroll
            for (int ky = 0; ky < 3; ++ky)
#pragma unroll
                for (int kx = 0; kx < 3; ++kx) {
                    ull vv[4];
#pragma unroll
                    for (int p = 0; p < 4; ++p)
                        vv[p] = pack2(v[ky][kx + p], v[ky][kx + p]);
                    if constexpr ((OCB & 3) == 0) {
#pragma unroll
                        for (int q = 0; q < OCB / 4; ++q) {
                            ulonglong2 wq = *reinterpret_cast<const ulonglong2*>(
                                &wsm[ics][ky * 3 + kx][q * 4]);
#pragma unroll
                            for (int p = 0; p < 4; ++p) {
                                fma2(acc[2 * q][p],     vv[p], wq.x);
                                fma2(acc[2 * q + 1][p], vv[p], wq.y);
                            }
                        }
                    } else {
#pragma unroll
                        for (int op = 0; op < NP; ++op) {
                            ull wp = *reinterpret_cast<const ull*>(
                                &wsm[ics][ky * 3 + kx][op * 2]);
#pragma unroll
                            for (int p = 0; p < 4; ++p)
                                fma2(acc[op][p], vv[p], wp);
                        }
                    }
                }
        }
    }

    const int py = by + ty;
    const int px = bx + tx * 4;
#pragma unroll
    for (int op = 0; op < NP; ++op) {
        float2 a[4];
#pragma unroll
        for (int p = 0; p < 4; ++p) a[p] = unpack2(acc[op][p]);
        int oce = oc0 + 2 * op;
#pragma unroll
        for (int lane = 0; lane < 2; ++lane) {
            int oc = oce + lane;
            if (oc >= OC) continue;
            float bv = bias[oc];
            float rr[4];
#pragma unroll
            for (int p = 0; p < 4; ++p) {
                float vv = (lane == 0 ? a[p].x : a[p].y) + bv;
                if (ACT == 1) vv = (vv >= 0.f) ? vv : 0.1f * vv;
                if (ACT == 2) vv = fmaxf(vv, 0.f);
                rr[p] = vv;
            }
            float4 r4; r4.x = rr[0]; r4.y = rr[1]; r4.z = rr[2]; r4.w = rr[3];
            *reinterpret_cast<float4*>(
                &out[((size_t)b * OC + oc) * HW + (size_t)py * WW + px]) = r4;
        }
    }
}

// ---------------------------------------------------------------------------
// Deformable conv core. Thread = 1 pixel, 32 f32x2 oc-pair accumulators.
// Per tap k: stage 64x64 weight slice transposed [c][oc], bilinear corner
// weights (mask folded) once; per channel: 4 coalesced corner loads -> sample
// s (lane-duplicated), 16 LDS.128 weight loads, 32 packed FMAs.
// ---------------------------------------------------------------------------
__global__ __launch_bounds__(256, 2)
void dcn_kernel(const float* __restrict__ x, const float* __restrict__ om,
                const float* __restrict__ wd, const float* __restrict__ bias,
                float* __restrict__ out)
{
    __shared__ __align__(16) float wk[64 * 64];   // [c][oc] for current k

    const int tid  = threadIdx.x;
    const int px0  = tid & 127;
    const int wrow = tid >> 7;
    const int b    = blockIdx.y;
    const int py0  = blockIdx.x * 2 + wrow;
    const int hw   = py0 * WW + px0;

    const float* omb = om + (size_t)b * 27 * HW;
    const float* xb  = x  + (size_t)b * 64 * HW;

    ull acc[32];
#pragma unroll
    for (int o = 0; o < 32; ++o) acc[o] = 0ull;

    for (int k = 0; k < 9; ++k) {
        __syncthreads();
        for (int i = tid; i < 4096; i += 256) {
            int c = i >> 6, oc = i & 63;
            wk[i] = wd[((size_t)oc * 64 + c) * 9 + k];   // transpose to [c][oc]
        }
        __syncthreads();

        float oy = omb[(size_t)k * HW + hw];
        float ox = omb[(size_t)(9 + k) * HW + hw];
        float mr = omb[(size_t)(18 + k) * HW + hw];
        float m  = 1.f / (1.f + __expf(-mr));

        int   ky = k / 3, kx = k - ky * 3;
        float py = (float)(py0 - 1 + ky) + oy;
        float px = (float)(px0 - 1 + kx) + ox;
        float y0f = floorf(py), x0f = floorf(px);
        float ly = py - y0f, lx = px - x0f;
        int y0 = (int)y0f, x0 = (int)x0f;
        int y1 = y0 + 1,   x1 = x0 + 1;

        float vy0 = (y0 >= 0 && y0 <= HH - 1) ? 1.f : 0.f;
        float vy1 = (y1 >= 0 && y1 <= HH - 1) ? 1.f : 0.f;
        float vx0 = (x0 >= 0 && x0 <= WW - 1) ? 1.f : 0.f;
        float vx1 = (x1 >= 0 && x1 <= WW - 1) ? 1.f : 0.f;
        int y0c = min(max(y0, 0), HH - 1), y1c = min(max(y1, 0), HH - 1);
        int x0c = min(max(x0, 0), WW - 1), x1c = min(max(x1, 0), WW - 1);

        float w00 = (1.f - ly) * (1.f - lx) * m * vy0 * vx0;
        float w01 = (1.f - ly) * lx         * m * vy0 * vx1;
        float w10 = ly         * (1.f - lx) * m * vy1 * vx0;
        float w11 = ly         * lx         * m * vy1 * vx1;

        int i00 = y0c * WW + x0c, i01 = y0c * WW + x1c;
        int i10 = y1c * WW + x0c, i11 = y1c * WW + x1c;

        const float* xc = xb;
        for (int c = 0; c < 64; ++c, xc += HW) {
            float s = w00 * xc[i00];
            s = fmaf(w01, xc[i01], s);
            s = fmaf(w10, xc[i10], s);
            s = fmaf(w11, xc[i11], s);
            ull ss = pack2(s, s);
            const ulonglong2* wr = reinterpret_cast<const ulonglong2*>(&wk[c * 64]);
#pragma unroll
            for (int j = 0; j < 16; ++j) {
                ulonglong2 q = wr[j];
                fma2(acc[2 * j],     ss, q.x);
                fma2(acc[2 * j + 1], ss, q.y);
            }
        }
    }

#pragma unroll
    for (int j = 0; j < 32; ++j) {
        float2 a = unpack2(acc[j]);
        int oc = 2 * j;
        out[((size_t)b * 64 + oc)     * HW + hw] = a.x + bias[oc];
        out[((size_t)b * 64 + oc + 1) * HW + hw] = a.y + bias[oc + 1];
    }
}

// ---------------------------------------------------------------------------
extern "C" void kernel_launch(void* const* d_in, const int* in_sizes, int n_in,
                              void* d_out, int out_size)
{
    const float* x        = (const float*)d_in[0];
    const float* x_neigh  = (const float*)d_in[1];
    const float* offset_t = (const float*)d_in[2];
    const float* w_off1   = (const float*)d_in[3];
    const float* b_off1   = (const float*)d_in[4];
    const float* w_off2   = (const float*)d_in[5];
    const float* b_off2   = (const float*)d_in[6];
    const float* w_off3   = (const float*)d_in[7];
    const float* b_off3   = (const float*)d_in[8];
    const float* w_om     = (const float*)d_in[9];
    const float* b_om     = (const float*)d_in[10];
    const float* w_dcn    = (const float*)d_in[11];
    const float* b_dcn    = (const float*)d_in[12];
    const float* w_outw   = (const float*)d_in[13];
    const float* b_outw   = (const float*)d_in[14];

    float* out        = (float*)d_out;
    float* out_align  = out;                              // (4,64,128,128)
    float* out_offset = out + (size_t)BB * 64 * HW;       // (4,64,128,128)

    float *p1, *p2, *pom, *pal;
    cudaGetSymbolAddress((void**)&p1,  g_buf1);
    cudaGetSymbolAddress((void**)&p2,  g_buf2);
    cudaGetSymbolAddress((void**)&pom, g_om);
    cudaGetSymbolAddress((void**)&pal, g_align);

    dim3 blk(256);
    dim3 g64(2, 8, BB * 4);   // 64 oc, OCB=16 -> 4 oc-blocks
    dim3 gom(2, 8, BB * 2);   // 27 oc, OCB=14 -> 2 oc-blocks (guarded)

    conv3x3_kernel<128, 16, 1><<<g64, blk>>>(x, x_neigh, w_off1, b_off1, p1, 4, 64);
    conv3x3_kernel<128, 16, 1><<<g64, blk>>>(p1, offset_t, w_off2, b_off2, p2, 4, 64);
    conv3x3_kernel<64, 16, 1><<<g64, blk>>>(p2, nullptr, w_off3, b_off3, out_offset, 4, 64);
    conv3x3_kernel<64, 14, 0><<<gom, blk>>>(out_offset, nullptr, w_om, b_om, pom, 2, 27);

    dim3 gd(64, BB);
    dcn_kernel<<<gd, blk>>>(x, pom, w_dcn, b_dcn, pal);

    conv3x3_kernel<64, 16, 2><<<g64, blk>>>(pal, nullptr, w_outw, b_outw, out_align, 4, 64);
}

// round 3
// speedup vs baseline: 1.3396x; 1.0097x over previous
#include <cuda_runtime.h>

#define HH 128
#define WW 128
#define HW (HH * WW)
#define BB 4

typedef unsigned long long ull;

__device__ __forceinline__ ull pack2(float lo, float hi) {
    ull r; asm("mov.b64 %0,{%1,%2};" : "=l"(r) : "f"(lo), "f"(hi)); return r;
}
__device__ __forceinline__ float2 unpack2(ull v) {
    float2 r; asm("mov.b64 {%0,%1},%2;" : "=f"(r.x), "=f"(r.y) : "l"(v)); return r;
}
// d = a*b + d  (two independent fp32 FMAs per instruction)
__device__ __forceinline__ void fma2(ull& d, ull a, ull b) {
    asm("fma.rn.f32x2 %0,%1,%2,%0;" : "+l"(d) : "l"(a), "l"(b));
}

// Scratch (allocation-free rule: __device__ globals)
__device__ float g_buf1[(size_t)BB * 64 * HW];   // offset_1
__device__ float g_buf2[(size_t)BB * 64 * HW];   // offset_2
__device__ float g_om  [(size_t)BB * 27 * HW];   // offset/mask conv output
__device__ float g_align[(size_t)BB * 64 * HW];  // dcn output (pre out-conv)

// ---------------------------------------------------------------------------
// 3x3 SAME conv, NCHW, OIHW. Tile 64(w) x 8(h). 256 threads =
// 16(tx) x 8(ty) x 2(oc-group). Thread = 1x4 px x 8 oc (4 f32x2 pairs).
// Block covers 16 output channels (2 groups of 8). 4 ic staged per phase.
// IC may be 128 (two-pointer concat). ACT: 0 none, 1 lrelu(0.1), 2 relu.
// ---------------------------------------------------------------------------
template<int IC, int ACT>
__global__ __launch_bounds__(256, 3)
void conv3x3_kernel(const float* __restrict__ in0, const float* __restrict__ in1,
                    const float* __restrict__ w, const float* __restrict__ bias,
                    float* __restrict__ out, int n_ocb, int OC)
{
    constexpr int ICS = 4;
    constexpr int RS  = 68;                  // padded patch row stride
    constexpr int PH  = 10;                  // 8 rows + halo

    __shared__ __align__(16) float patch[ICS][PH * RS];
    __shared__ __align__(16) float wsm[ICS][9][16];

    const int tid = threadIdx.x;
    const int tx  = tid & 15;
    const int ty  = (tid >> 4) & 7;
    const int og  = tid >> 7;                // 0/1: which 8-oc half
    const int bx  = blockIdx.x * 64;
    const int by  = blockIdx.y * 8;
    const int b   = blockIdx.z / n_ocb;
    const int ocb = blockIdx.z - b * n_ocb;
    const int oc0 = ocb * 16 + og * 8;       // this thread's first oc

    ull acc[4][4];                           // [oc pair][px]
#pragma unroll
    for (int o = 0; o < 4; ++o)
#pragma unroll
        for (int p = 0; p < 4; ++p) acc[o][p] = 0ull;

    for (int ic0 = 0; ic0 < IC; ic0 += ICS) {
        __syncthreads();
        // stage ICS halo patches (10 x 66 valid, stride 68)
        for (int i = tid; i < ICS * PH * RS; i += 256) {
            int ics = i / (PH * RS);
            int r2  = i - ics * (PH * RS);
            int r   = r2 / RS, c = r2 - r * RS;
            int gy = by + r - 1, gx = bx + c - 1;
            float v = 0.f;
            if (c < 66 && (unsigned)gy < HH && (unsigned)gx < WW) {
                int ic = ic0 + ics;
                const float* src;
                if (IC > 64 && ic >= 64)
                    src = in1 + ((size_t)b * 64 + (ic - 64)) * HW;
                else
                    src = in0 + ((size_t)b * 64 + ic) * HW;
                v = src[gy * WW + gx];
            }
            patch[ics][r2] = v;
        }
        // stage weights: 16 oc contiguous per (ics, tap)
        for (int i = tid; i < ICS * 9 * 16; i += 256) {
            int ics = i / (9 * 16);
            int r   = i - ics * (9 * 16);
            int k   = r >> 4;
            int oc  = r & 15;
            int ocg = ocb * 16 + oc;
            wsm[ics][k][oc] = (ocg < OC) ? w[((size_t)ocg * IC + ic0 + ics) * 9 + k] : 0.f;
        }
        __syncthreads();

#pragma unroll
        for (int ics = 0; ics < ICS; ++ics) {
            float v[3][6];
            const float* prow = patch[ics];
#pragma unroll
            for (int r = 0; r < 3; ++r) {
                int base = (ty + r) * RS + tx * 4;
                float4 v4 = *reinterpret_cast<const float4*>(&prow[base]);
                float2 v2 = *reinterpret_cast<const float2*>(&prow[base + 4]);
                v[r][0] = v4.x; v[r][1] = v4.y; v[r][2] = v4.z; v[r][3] = v4.w;
                v[r][4] = v2.x; v[r][5] = v2.y;
            }
#pragma unroll
            for (int ky = 0; ky < 3; ++ky)
#pragma unroll
                for (int kx = 0; kx < 3; ++kx) {
                    ull vv[4];
#pragma unroll
                    for (int p = 0; p < 4; ++p)
                        vv[p] = pack2(v[ky][kx + p], v[ky][kx + p]);
                    const ulonglong2* wr = reinterpret_cast<const ulonglong2*>(
                        &wsm[ics][ky * 3 + kx][og * 8]);
#pragma unroll
                    for (int q = 0; q < 2; ++q) {
                        ulonglong2 wq = wr[q];             // 4 weights, LDS.128
#pragma unroll
                        for (int p = 0; p < 4; ++p) {
                            fma2(acc[2 * q][p],     vv[p], wq.x);
                            fma2(acc[2 * q + 1][p], vv[p], wq.y);
                        }
                    }
                }
        }
    }

    const int py = by + ty;
    const int px = bx + tx * 4;
#pragma unroll
    for (int op = 0; op < 4; ++op) {
        float2 a[4];
#pragma unroll
        for (int p = 0; p < 4; ++p) a[p] = unpack2(acc[op][p]);
        int oce = oc0 + 2 * op;
#pragma unroll
        for (int lane = 0; lane < 2; ++lane) {
            int oc = oce + lane;
            if (oc >= OC) continue;
            float bv = bias[oc];
            float rr[4];
#pragma unroll
            for (int p = 0; p < 4; ++p) {
                float vv = (lane == 0 ? a[p].x : a[p].y) + bv;
                if (ACT == 1) vv = (vv >= 0.f) ? vv : 0.1f * vv;
                if (ACT == 2) vv = fmaxf(vv, 0.f);
                rr[p] = vv;
            }
            float4 r4; r4.x = rr[0]; r4.y = rr[1]; r4.z = rr[2]; r4.w = rr[3];
            *reinterpret_cast<float4*>(
                &out[((size_t)b * OC + oc) * HW + (size_t)py * WW + px]) = r4;
        }
    }
}

// ---------------------------------------------------------------------------
// Deformable conv core. Thread = 1 pixel, 32 f32x2 oc-pair accumulators.
// Per tap k: stage 64x64 weight slice transposed [c][oc], bilinear corner
// weights (mask folded) once; per channel: 4 coalesced corner loads -> sample
// s (lane-duplicated), 16 LDS.128 weight loads, 32 packed FMAs.
// ---------------------------------------------------------------------------
__global__ __launch_bounds__(256, 2)
void dcn_kernel(const float* __restrict__ x, const float* __restrict__ om,
                const float* __restrict__ wd, const float* __restrict__ bias,
                float* __restrict__ out)
{
    __shared__ __align__(16) float wk[64 * 64];   // [c][oc] for current k

    const int tid  = threadIdx.x;
    const int px0  = tid & 127;
    const int wrow = tid >> 7;
    const int b    = blockIdx.y;
    const int py0  = blockIdx.x * 2 + wrow;
    const int hw   = py0 * WW + px0;

    const float* omb = om + (size_t)b * 27 * HW;
    const float* xb  = x  + (size_t)b * 64 * HW;

    ull acc[32];
#pragma unroll
    for (int o = 0; o < 32; ++o) acc[o] = 0ull;

    for (int k = 0; k < 9; ++k) {
        __syncthreads();
        for (int i = tid; i < 4096; i += 256) {
            int c = i >> 6, oc = i & 63;
            wk[i] = wd[((size_t)oc * 64 + c) * 9 + k];   // transpose to [c][oc]
        }
        __syncthreads();

        float oy = omb[(size_t)k * HW + hw];
        float ox = omb[(size_t)(9 + k) * HW + hw];
        float mr = omb[(size_t)(18 + k) * HW + hw];
        float m  = 1.f / (1.f + __expf(-mr));

        int   ky = k / 3, kx = k - ky * 3;
        float py = (float)(py0 - 1 + ky) + oy;
        float px = (float)(px0 - 1 + kx) + ox;
        float y0f = floorf(py), x0f = floorf(px);
        float ly = py - y0f, lx = px - x0f;
        int y0 = (int)y0f, x0 = (int)x0f;
        int y1 = y0 + 1,   x1 = x0 + 1;

        float vy0 = (y0 >= 0 && y0 <= HH - 1) ? 1.f : 0.f;
        float vy1 = (y1 >= 0 && y1 <= HH - 1) ? 1.f : 0.f;
        float vx0 = (x0 >= 0 && x0 <= WW - 1) ? 1.f : 0.f;
        float vx1 = (x1 >= 0 && x1 <= WW - 1) ? 1.f : 0.f;
        int y0c = min(max(y0, 0), HH - 1), y1c = min(max(y1, 0), HH - 1);
        int x0c = min(max(x0, 0), WW - 1), x1c = min(max(x1, 0), WW - 1);

        float w00 = (1.f - ly) * (1.f - lx) * m * vy0 * vx0;
        float w01 = (1.f - ly) * lx         * m * vy0 * vx1;
        float w10 = ly         * (1.f - lx) * m * vy1 * vx0;
        float w11 = ly         * lx         * m * vy1 * vx1;

        int i00 = y0c * WW + x0c, i01 = y0c * WW + x1c;
        int i10 = y1c * WW + x0c, i11 = y1c * WW + x1c;

        const float* xc = xb;
        for (int c = 0; c < 64; ++c, xc += HW) {
            float s = w00 * xc[i00];
            s = fmaf(w01, xc[i01], s);
            s = fmaf(w10, xc[i10], s);
            s = fmaf(w11, xc[i11], s);
            ull ss = pack2(s, s);
            const ulonglong2* wr = reinterpret_cast<const ulonglong2*>(&wk[c * 64]);
#pragma unroll
            for (int j = 0; j < 16; ++j) {
                ulonglong2 q = wr[j];
                fma2(acc[2 * j],     ss, q.x);
                fma2(acc[2 * j + 1], ss, q.y);
            }
        }
    }

#pragma unroll
    for (int j = 0; j < 32; ++j) {
        float2 a = unpack2(acc[j]);
        int oc = 2 * j;
        out[((size_t)b * 64 + oc)     * HW + hw] = a.x + bias[oc];
        out[((size_t)b * 64 + oc + 1) * HW + hw] = a.y + bias[oc + 1];
    }
}

// ---------------------------------------------------------------------------
extern "C" void kernel_launch(void* const* d_in, const int* in_sizes, int n_in,
                              void* d_out, int out_size)
{
    const float* x        = (const float*)d_in[0];
    const float* x_neigh  = (const float*)d_in[1];
    const float* offset_t = (const float*)d_in[2];
    const float* w_off1   = (const float*)d_in[3];
    const float* b_off1   = (const float*)d_in[4];
    const float* w_off2   = (const float*)d_in[5];
    const float* b_off2   = (const float*)d_in[6];
    const float* w_off3   = (const float*)d_in[7];
    const float* b_off3   = (const float*)d_in[8];
    const float* w_om     = (const float*)d_in[9];
    const float* b_om     = (const float*)d_in[10];
    const float* w_dcn    = (const float*)d_in[11];
    const float* b_dcn    = (const float*)d_in[12];
    const float* w_outw   = (const float*)d_in[13];
    const float* b_outw   = (const float*)d_in[14];

    float* out        = (float*)d_out;
    float* out_align  = out;                              // (4,64,128,128)
    float* out_offset = out + (size_t)BB * 64 * HW;       // (4,64,128,128)

    float *p1, *p2, *pom, *pal;
    cudaGetSymbolAddress((void**)&p1,  g_buf1);
    cudaGetSymbolAddress((void**)&p2,  g_buf2);
    cudaGetSymbolAddress((void**)&pom, g_om);
    cudaGetSymbolAddress((void**)&pal, g_align);

    dim3 blk(256);
    dim3 g64(2, 16, BB * 4);  // 64 oc -> 4 oc-blocks of 16; 512 blocks
    dim3 gom(2, 16, BB * 2);  // 27 oc -> 2 oc-blocks of 16 (guarded); 256 blocks

    conv3x3_kernel<128, 1><<<g64, blk>>>(x, x_neigh, w_off1, b_off1, p1, 4, 64);
    conv3x3_kernel<128, 1><<<g64, blk>>>(p1, offset_t, w_off2, b_off2, p2, 4, 64);
    conv3x3_kernel<64, 1><<<g64, blk>>>(p2, nullptr, w_off3, b_off3, out_offset, 4, 64);
    conv3x3_kernel<64, 0><<<gom, blk>>>(out_offset, nullptr, w_om, b_om, pom, 2, 27);

    dim3 gd(64, BB);
    dcn_kernel<<<gd, blk>>>(x, pom, w_dcn, b_dcn, pal);

    conv3x3_kernel<64, 2><<<g64, blk>>>(pal, nullptr, w_outw, b_outw, out_align, 4, 64);
}